// round 2
// baseline (speedup 1.0000x reference)
#include <cuda_runtime.h>

// LIF membrane update, HBM-streaming:
//   mem_t = (mem_{t-1} - spike_{t-1} * 0.5) * 0.25 + x_t
//   spike_t = rint(clamp(mem_t, 0, 1))
// x: [T=4, N] fp32, out: [T=4, N] fp32. Per-element recurrence over t.
// ILP=2 float4 per thread (8 loads in flight), streaming cache hints (zero reuse).

#define DECAY 0.25f
#define T_STEPS 4

__global__ __launch_bounds__(256) void lif_kernel(const float4* __restrict__ x,
                                                  float4* __restrict__ out,
                                                  int n4) {
    // Each thread handles two consecutive float4s: indices 2*i and 2*i+1.
    int i = (blockIdx.x * blockDim.x + threadIdx.x) * 2;
    if (i + 1 >= n4) {
        // Tail (only possible if n4 odd — not the case here, but be safe)
        if (i < n4) {
            float4 mem = make_float4(0.f, 0.f, 0.f, 0.f);
            float4 spk = make_float4(0.f, 0.f, 0.f, 0.f);
#pragma unroll
            for (int t = 0; t < T_STEPS; t++) {
                float4 xi = __ldcs(&x[(size_t)t * n4 + i]);
                mem.x = fmaf(mem.x - spk.x * 0.5f, DECAY, xi.x);
                mem.y = fmaf(mem.y - spk.y * 0.5f, DECAY, xi.y);
                mem.z = fmaf(mem.z - spk.z * 0.5f, DECAY, xi.z);
                mem.w = fmaf(mem.w - spk.w * 0.5f, DECAY, xi.w);
                spk.x = rintf(fminf(fmaxf(mem.x, 0.f), 1.f));
                spk.y = rintf(fminf(fmaxf(mem.y, 0.f), 1.f));
                spk.z = rintf(fminf(fmaxf(mem.z, 0.f), 1.f));
                spk.w = rintf(fminf(fmaxf(mem.w, 0.f), 1.f));
                __stcs(&out[(size_t)t * n4 + i], spk);
            }
        }
        return;
    }

    float4 mem0 = make_float4(0.f, 0.f, 0.f, 0.f);
    float4 mem1 = make_float4(0.f, 0.f, 0.f, 0.f);
    float4 spk0 = make_float4(0.f, 0.f, 0.f, 0.f);
    float4 spk1 = make_float4(0.f, 0.f, 0.f, 0.f);

#pragma unroll
    for (int t = 0; t < T_STEPS; t++) {
        const float4* xt = x + (size_t)t * n4 + i;
        float4 xi0 = __ldcs(xt);
        float4 xi1 = __ldcs(xt + 1);

        mem0.x = fmaf(mem0.x - spk0.x * 0.5f, DECAY, xi0.x);
        mem0.y = fmaf(mem0.y - spk0.y * 0.5f, DECAY, xi0.y);
        mem0.z = fmaf(mem0.z - spk0.z * 0.5f, DECAY, xi0.z);
        mem0.w = fmaf(mem0.w - spk0.w * 0.5f, DECAY, xi0.w);
        mem1.x = fmaf(mem1.x - spk1.x * 0.5f, DECAY, xi1.x);
        mem1.y = fmaf(mem1.y - spk1.y * 0.5f, DECAY, xi1.y);
        mem1.z = fmaf(mem1.z - spk1.z * 0.5f, DECAY, xi1.z);
        mem1.w = fmaf(mem1.w - spk1.w * 0.5f, DECAY, xi1.w);

        spk0.x = rintf(fminf(fmaxf(mem0.x, 0.f), 1.f));
        spk0.y = rintf(fminf(fmaxf(mem0.y, 0.f), 1.f));
        spk0.z = rintf(fminf(fmaxf(mem0.z, 0.f), 1.f));
        spk0.w = rintf(fminf(fmaxf(mem0.w, 0.f), 1.f));
        spk1.x = rintf(fminf(fmaxf(mem1.x, 0.f), 1.f));
        spk1.y = rintf(fminf(fmaxf(mem1.y, 0.f), 1.f));
        spk1.z = rintf(fminf(fmaxf(mem1.z, 0.f), 1.f));
        spk1.w = rintf(fminf(fmaxf(mem1.w, 0.f), 1.f));

        float4* ot = out + (size_t)t * n4 + i;
        __stcs(ot, spk0);
        __stcs(ot + 1, spk1);
    }
}

extern "C" void kernel_launch(void* const* d_in, const int* in_sizes, int n_in,
                              void* d_out, int out_size) {
    const float4* x = (const float4*)d_in[0];
    float4* out = (float4*)d_out;

    int n_total = in_sizes[0];        // T * N
    int n4 = (n_total / T_STEPS) / 4; // float4 elements per timestep

    int threads = 256;
    int elems_per_block = threads * 2;
    int blocks = (n4 + elems_per_block - 1) / elems_per_block;
    lif_kernel<<<blocks, threads>>>(x, out, n4);
}

// round 3
// speedup vs baseline: 1.0156x; 1.0156x over previous
#include <cuda_runtime.h>

// LIF membrane update, HBM-streaming:
//   mem_t = (mem_{t-1} - spike_{t-1} * 0.5) * 0.25 + x_t
//   spike_t = rint(clamp(mem_t, 0, 1))
// x: [T=4, N] fp32, out: [T=4, N] fp32. Per-element recurrence over t.
// ILP=2 float4 per thread with COALESCED layout (thread owns i and i+blockDim)
// so every LDG.128 stays lane-contiguous. 8 independent loads in flight/thread.

#define DECAY 0.25f
#define T_STEPS 4

__device__ __forceinline__ float4 lif_step(float4& mem, const float4& spk, const float4& xi) {
    mem.x = fmaf(mem.x - spk.x * 0.5f, DECAY, xi.x);
    mem.y = fmaf(mem.y - spk.y * 0.5f, DECAY, xi.y);
    mem.z = fmaf(mem.z - spk.z * 0.5f, DECAY, xi.z);
    mem.w = fmaf(mem.w - spk.w * 0.5f, DECAY, xi.w);
    float4 s;
    s.x = rintf(fminf(fmaxf(mem.x, 0.f), 1.f));
    s.y = rintf(fminf(fmaxf(mem.y, 0.f), 1.f));
    s.z = rintf(fminf(fmaxf(mem.z, 0.f), 1.f));
    s.w = rintf(fminf(fmaxf(mem.w, 0.f), 1.f));
    return s;
}

__global__ __launch_bounds__(256) void lif_kernel(const float4* __restrict__ x,
                                                  float4* __restrict__ out,
                                                  int n4) {
    // Block covers a contiguous span of 2*blockDim float4s:
    //   lane slot 0: base + tid            (coalesced across warp)
    //   lane slot 1: base + tid + blockDim (coalesced across warp)
    int base = blockIdx.x * (blockDim.x * 2);
    int i0 = base + threadIdx.x;
    int i1 = i0 + blockDim.x;

    bool v0 = (i0 < n4);
    bool v1 = (i1 < n4);

    float4 mem0 = make_float4(0.f, 0.f, 0.f, 0.f);
    float4 mem1 = make_float4(0.f, 0.f, 0.f, 0.f);
    float4 spk0 = make_float4(0.f, 0.f, 0.f, 0.f);
    float4 spk1 = make_float4(0.f, 0.f, 0.f, 0.f);

#pragma unroll
    for (int t = 0; t < T_STEPS; t++) {
        size_t off = (size_t)t * n4;
        float4 xi0 = v0 ? __ldcs(&x[off + i0]) : make_float4(0.f, 0.f, 0.f, 0.f);
        float4 xi1 = v1 ? __ldcs(&x[off + i1]) : make_float4(0.f, 0.f, 0.f, 0.f);

        spk0 = lif_step(mem0, spk0, xi0);
        spk1 = lif_step(mem1, spk1, xi1);

        if (v0) __stcs(&out[off + i0], spk0);
        if (v1) __stcs(&out[off + i1], spk1);
    }
}

extern "C" void kernel_launch(void* const* d_in, const int* in_sizes, int n_in,
                              void* d_out, int out_size) {
    const float4* x = (const float4*)d_in[0];
    float4* out = (float4*)d_out;

    int n_total = in_sizes[0];        // T * N
    int n4 = (n_total / T_STEPS) / 4; // float4 elements per timestep

    int threads = 256;
    int elems_per_block = threads * 2;
    int blocks = (n4 + elems_per_block - 1) / elems_per_block;
    lif_kernel<<<blocks, threads>>>(x, out, n4);
}

// round 4
// speedup vs baseline: 1.0538x; 1.0376x over previous
#include <cuda_runtime.h>

// LIF membrane update, HBM-streaming (pure stream, zero reuse):
//   mem_t = (mem_{t-1} - spike_{t-1} * 0.5) * 0.25 + x_t
//   spike_t = rint(clamp(mem_t, 0, 1))
// x: [T=4, N] fp32, out: [T=4, N] fp32.
// One float4 per thread (R1 layout = best measured). Phase-split: all 4
// timestep loads issued front-batched, then compute chain, then 4 stores —
// keeps the LSU queue pure-load during the latency-critical window.

#define DECAY 0.25f
#define T_STEPS 4

__global__ __launch_bounds__(256) void lif_kernel(const float4* __restrict__ x,
                                                  float4* __restrict__ out,
                                                  int n4) {
    int i = blockIdx.x * blockDim.x + threadIdx.x;
    if (i >= n4) return;

    // Phase 1: front-batch all 4 independent loads (MLP_p1 = 4, no STG between).
    float4 xi[T_STEPS];
#pragma unroll
    for (int t = 0; t < T_STEPS; t++) {
        xi[t] = __ldcs(&x[(size_t)t * n4 + i]);
    }

    // Phase 2: serial recurrence entirely in registers.
    float4 spk[T_STEPS];
    float4 mem = make_float4(0.f, 0.f, 0.f, 0.f);
    float4 s = make_float4(0.f, 0.f, 0.f, 0.f);
#pragma unroll
    for (int t = 0; t < T_STEPS; t++) {
        mem.x = fmaf(mem.x - s.x * 0.5f, DECAY, xi[t].x);
        mem.y = fmaf(mem.y - s.y * 0.5f, DECAY, xi[t].y);
        mem.z = fmaf(mem.z - s.z * 0.5f, DECAY, xi[t].z);
        mem.w = fmaf(mem.w - s.w * 0.5f, DECAY, xi[t].w);
        s.x = rintf(fminf(fmaxf(mem.x, 0.f), 1.f));
        s.y = rintf(fminf(fmaxf(mem.y, 0.f), 1.f));
        s.z = rintf(fminf(fmaxf(mem.z, 0.f), 1.f));
        s.w = rintf(fminf(fmaxf(mem.w, 0.f), 1.f));
        spk[t] = s;
    }

    // Phase 3: drain all 4 stores.
#pragma unroll
    for (int t = 0; t < T_STEPS; t++) {
        __stcs(&out[(size_t)t * n4 + i], spk[t]);
    }
}

extern "C" void kernel_launch(void* const* d_in, const int* in_sizes, int n_in,
                              void* d_out, int out_size) {
    const float4* x = (const float4*)d_in[0];
    float4* out = (float4*)d_out;

    int n_total = in_sizes[0];        // T * N
    int n4 = (n_total / T_STEPS) / 4; // float4 elements per timestep

    int threads = 256;
    int blocks = (n4 + threads - 1) / threads;
    lif_kernel<<<blocks, threads>>>(x, out, n4);
}